// round 1
// baseline (speedup 1.0000x reference)
#include <cuda_runtime.h>
#include <math.h>

#define BB 4
#define NX 4096
#define NY 4096
#define FF 16

// Precomputed per-point scratch (no dynamic allocation allowed)
__device__ float g_cx[BB * NX];   // ||x||^2
__device__ float g_ssx[BB * NX];  // sqrt(clip(sample_x . s, 1e-10, 1e6))
__device__ float g_cy[BB * NY];
__device__ float g_ssy[BB * NY];

// ---------------------------------------------------------------------------
// Pass 1: per-point sq-norm and sqrt of clipped scale-dot. 32768 points total.
// ---------------------------------------------------------------------------
__global__ void precompute_kernel(const float* __restrict__ pts,
                                  const float* __restrict__ samp,
                                  const float* __restrict__ scale,
                                  float* __restrict__ c_out,
                                  float* __restrict__ ss_out,
                                  int n) {
    __shared__ float s[FF];
    if (threadIdx.x < FF) {
        s[threadIdx.x] = fminf(fmaxf(scale[threadIdx.x], 1e-6f), 1e6f);
    }
    __syncthreads();

    int i = blockIdx.x * blockDim.x + threadIdx.x;
    if (i >= n) return;

    float p0 = pts[i * 3 + 0];
    float p1 = pts[i * 3 + 1];
    float p2 = pts[i * 3 + 2];
    float c = p0 * p0 + p1 * p1 + p2 * p2;

    const float4* sp = reinterpret_cast<const float4*>(samp + (size_t)i * FF);
    float dot = 0.0f;
#pragma unroll
    for (int q = 0; q < FF / 4; q++) {
        float4 v = sp[q];
        dot = fmaf(v.x, s[q * 4 + 0], dot);
        dot = fmaf(v.y, s[q * 4 + 1], dot);
        dot = fmaf(v.z, s[q * 4 + 2], dot);
        dot = fmaf(v.w, s[q * 4 + 3], dot);
    }
    float sx = fminf(fmaxf(dot, 1e-10f), 1e6f);

    c_out[i] = c;
    ss_out[i] = sqrtf(sx);
}

// ---------------------------------------------------------------------------
// Pass 2: main pairwise kernel.
// Block: 256 threads -> tile of TI=16 rows x 1024 cols (4 cols/thread, float4).
// Grid: (NY/1024, NX/TI, B)
// ---------------------------------------------------------------------------
#define TI 16
#define TJ_THREAD 4
#define THREADS 256
#define TJ (THREADS * TJ_THREAD)  // 1024

__global__ __launch_bounds__(THREADS)
void cauchy_main_kernel(const float* __restrict__ x,
                        const float* __restrict__ y,
                        float* __restrict__ out) {
    const int b = blockIdx.z;
    const int i0 = blockIdx.y * TI;
    const int j0 = blockIdx.x * TJ + threadIdx.x * TJ_THREAD;

    __shared__ float sxa[TI], sxb[TI], sxc[TI], scx[TI], sssx[TI];
    if (threadIdx.x < TI) {
        int gi = b * NX + i0 + threadIdx.x;
        sxa[threadIdx.x] = -2.0f * x[gi * 3 + 0];
        sxb[threadIdx.x] = -2.0f * x[gi * 3 + 1];
        sxc[threadIdx.x] = -2.0f * x[gi * 3 + 2];
        scx[threadIdx.x] = g_cx[gi];
        sssx[threadIdx.x] = g_ssx[gi];
    }

    // Load this thread's 4 y-points: 12 contiguous floats -> 3 float4 loads
    const int gj = b * NY + j0;
    const float4* yp = reinterpret_cast<const float4*>(y + (size_t)gj * 3);
    float4 ya = yp[0];
    float4 yb = yp[1];
    float4 yc = yp[2];
    float y0[4] = {ya.x, ya.w, yb.z, yc.y};
    float y1[4] = {ya.y, yb.x, yb.w, yc.z};
    float y2[4] = {ya.z, yb.y, yc.x, yc.w};

    float4 cy4 = *reinterpret_cast<const float4*>(g_cy + gj);
    float4 sy4 = *reinterpret_cast<const float4*>(g_ssy + gj);
    float cyv[4] = {cy4.x, cy4.y, cy4.z, cy4.w};
    float syv[4] = {sy4.x, sy4.y, sy4.z, sy4.w};

    __syncthreads();

    float* orow = out + ((size_t)(b * NX + i0)) * NY + j0;

#pragma unroll 4
    for (int ti = 0; ti < TI; ti++) {
        float a0 = sxa[ti];
        float a1 = sxb[ti];
        float a2 = sxc[ti];
        float c = scx[ti];
        float sa = sssx[ti];

        float4 res;
        float r[4];
#pragma unroll
        for (int u = 0; u < 4; u++) {
            // d = cx + cy - 2*dot(x,y), folded into FMA chain with -2x
            float d = fmaf(a0, y0[u],
                      fmaf(a1, y1[u],
                      fmaf(a2, y2[u], c + cyv[u])));
            d = fminf(fmaxf(d, 1e-10f), 1e6f);
            // sqrt(clip(sx*sy,1e-10,1e12)) == clamp(sqrt(sx)*sqrt(sy),1e-5,1e6)
            float sxy = fminf(fmaxf(sa * syv[u], 1e-5f), 1e6f);
            // 1/(1 + d/sxy) == sxy/(sxy + d)
            r[u] = __fdividef(sxy, sxy + d);
        }
        res.x = r[0]; res.y = r[1]; res.z = r[2]; res.w = r[3];
        *reinterpret_cast<float4*>(orow + (size_t)ti * NY) = res;
    }
}

// ---------------------------------------------------------------------------
extern "C" void kernel_launch(void* const* d_in, const int* in_sizes, int n_in,
                              void* d_out, int out_size) {
    const float* x        = (const float*)d_in[0];  // (B,NX,3)
    const float* y        = (const float*)d_in[1];  // (B,NY,3)
    const float* sample_x = (const float*)d_in[2];  // (B,NX,F)
    const float* sample_y = (const float*)d_in[3];  // (B,NY,F)
    const float* scale    = (const float*)d_in[4];  // (F,)
    float* out = (float*)d_out;                     // (B,NX,NY)

    float* cx;  cudaGetSymbolAddress((void**)&cx,  g_cx);
    float* ssx; cudaGetSymbolAddress((void**)&ssx, g_ssx);
    float* cy;  cudaGetSymbolAddress((void**)&cy,  g_cy);
    float* ssy; cudaGetSymbolAddress((void**)&ssy, g_ssy);

    const int npts = BB * NX;  // == BB * NY
    precompute_kernel<<<(npts + 255) / 256, 256>>>(x, sample_x, scale, cx, ssx, npts);
    precompute_kernel<<<(npts + 255) / 256, 256>>>(y, sample_y, scale, cy, ssy, npts);

    dim3 grid(NY / TJ, NX / TI, BB);
    cauchy_main_kernel<<<grid, THREADS>>>(x, y, out);
}

// round 3
// speedup vs baseline: 1.0391x; 1.0391x over previous
#include <cuda_runtime.h>
#include <math.h>

#define BB 4
#define NX 4096
#define NY 4096
#define FF 16

// Precomputed per-point scratch (no dynamic allocation allowed)
__device__ float g_cx[BB * NX];   // ||x||^2
__device__ float g_ssx[BB * NX];  // sqrt(clip(sample_x . s, 1e-10, 1e6))
__device__ float g_cy[BB * NY];
__device__ float g_ssy[BB * NY];

// ---------------------------------------------------------------------------
// Pass 1 (fused): per-point sq-norm and sqrt of clipped scale-dot for BOTH
// x-side and y-side points in a single launch. 32768 points total.
// ---------------------------------------------------------------------------
__global__ void precompute_fused_kernel(const float* __restrict__ xpts,
                                        const float* __restrict__ xsamp,
                                        const float* __restrict__ ypts,
                                        const float* __restrict__ ysamp,
                                        const float* __restrict__ scale,
                                        float* __restrict__ cx_out,
                                        float* __restrict__ ssx_out,
                                        float* __restrict__ cy_out,
                                        float* __restrict__ ssy_out,
                                        int npts) {
    __shared__ float s[FF];
    if (threadIdx.x < FF) {
        s[threadIdx.x] = fminf(fmaxf(scale[threadIdx.x], 1e-6f), 1e6f);
    }
    __syncthreads();

    int gid = blockIdx.x * blockDim.x + threadIdx.x;
    int i = (gid < npts) ? gid : (gid - npts);
    if (gid >= 2 * npts) return;

    const float* pts   = (gid < npts) ? xpts  : ypts;
    const float* samp  = (gid < npts) ? xsamp : ysamp;
    float* c_out       = (gid < npts) ? cx_out  : cy_out;
    float* ss_out      = (gid < npts) ? ssx_out : ssy_out;

    float p0 = pts[i * 3 + 0];
    float p1 = pts[i * 3 + 1];
    float p2 = pts[i * 3 + 2];
    float c = p0 * p0 + p1 * p1 + p2 * p2;

    const float4* sp = reinterpret_cast<const float4*>(samp + (size_t)i * FF);
    float dot = 0.0f;
#pragma unroll
    for (int q = 0; q < FF / 4; q++) {
        float4 v = sp[q];
        dot = fmaf(v.x, s[q * 4 + 0], dot);
        dot = fmaf(v.y, s[q * 4 + 1], dot);
        dot = fmaf(v.z, s[q * 4 + 2], dot);
        dot = fmaf(v.w, s[q * 4 + 3], dot);
    }
    float sx = fminf(fmaxf(dot, 1e-10f), 1e6f);

    c_out[i] = c;
    ss_out[i] = sqrtf(sx);
}

// ---------------------------------------------------------------------------
// Pass 2: main pairwise kernel.
// Block: 256 threads -> tile of TI=16 rows x 1024 cols (4 cols/thread, float4).
// Grid: (NY/1024, NX/TI, B)
// ---------------------------------------------------------------------------
#define TI 16
#define TJ_THREAD 4
#define THREADS 256
#define TJ (THREADS * TJ_THREAD)  // 1024

__global__ __launch_bounds__(THREADS)
void cauchy_main_kernel(const float* __restrict__ x,
                        const float* __restrict__ y,
                        float* __restrict__ out) {
    const int b = blockIdx.z;
    const int i0 = blockIdx.y * TI;
    const int j0 = blockIdx.x * TJ + threadIdx.x * TJ_THREAD;

    __shared__ float sxa[TI], sxb[TI], sxc[TI], scx[TI], sssx[TI];
    if (threadIdx.x < TI) {
        int gi = b * NX + i0 + threadIdx.x;
        sxa[threadIdx.x] = -2.0f * x[gi * 3 + 0];
        sxb[threadIdx.x] = -2.0f * x[gi * 3 + 1];
        sxc[threadIdx.x] = -2.0f * x[gi * 3 + 2];
        scx[threadIdx.x] = g_cx[gi];
        sssx[threadIdx.x] = g_ssx[gi];
    }

    // Load this thread's 4 y-points: 12 contiguous floats -> 3 float4 loads
    const int gj = b * NY + j0;
    const float4* yp = reinterpret_cast<const float4*>(y + (size_t)gj * 3);
    float4 ya = yp[0];
    float4 yb = yp[1];
    float4 yc = yp[2];
    float y0[4] = {ya.x, ya.w, yb.z, yc.y};
    float y1[4] = {ya.y, yb.x, yb.w, yc.z};
    float y2[4] = {ya.z, yb.y, yc.x, yc.w};

    float4 cy4 = *reinterpret_cast<const float4*>(g_cy + gj);
    float4 sy4 = *reinterpret_cast<const float4*>(g_ssy + gj);
    float cyv[4] = {cy4.x, cy4.y, cy4.z, cy4.w};
    float syv[4] = {sy4.x, sy4.y, sy4.z, sy4.w};

    __syncthreads();

    float* orow = out + ((size_t)(b * NX + i0)) * NY + j0;

#pragma unroll 4
    for (int ti = 0; ti < TI; ti++) {
        float a0 = sxa[ti];
        float a1 = sxb[ti];
        float a2 = sxc[ti];
        float c = scx[ti];
        float sa = sssx[ti];

        float4 res;
        float r[4];
#pragma unroll
        for (int u = 0; u < 4; u++) {
            // d = cx + cy - 2*dot(x,y), folded into FMA chain with -2x
            float d = fmaf(a0, y0[u],
                      fmaf(a1, y1[u],
                      fmaf(a2, y2[u], c + cyv[u])));
            d = fminf(fmaxf(d, 1e-10f), 1e6f);
            // sqrt(clip(sx*sy,1e-10,1e12)) == clamp(sqrt(sx)*sqrt(sy),1e-5,1e6)
            float sxy = fminf(fmaxf(sa * syv[u], 1e-5f), 1e6f);
            // 1/(1 + d/sxy) == sxy/(sxy + d)
            r[u] = __fdividef(sxy, sxy + d);
        }
        res.x = r[0]; res.y = r[1]; res.z = r[2]; res.w = r[3];
        *reinterpret_cast<float4*>(orow + (size_t)ti * NY) = res;
    }
}

// ---------------------------------------------------------------------------
extern "C" void kernel_launch(void* const* d_in, const int* in_sizes, int n_in,
                              void* d_out, int out_size) {
    const float* x        = (const float*)d_in[0];  // (B,NX,3)
    const float* y        = (const float*)d_in[1];  // (B,NY,3)
    const float* sample_x = (const float*)d_in[2];  // (B,NX,F)
    const float* sample_y = (const float*)d_in[3];  // (B,NY,F)
    const float* scale    = (const float*)d_in[4];  // (F,)
    float* out = (float*)d_out;                     // (B,NX,NY)

    float* cx;  cudaGetSymbolAddress((void**)&cx,  g_cx);
    float* ssx; cudaGetSymbolAddress((void**)&ssx, g_ssx);
    float* cy;  cudaGetSymbolAddress((void**)&cy,  g_cy);
    float* ssy; cudaGetSymbolAddress((void**)&ssy, g_ssy);

    const int npts = BB * NX;  // == BB * NY
    precompute_fused_kernel<<<(2 * npts + 255) / 256, 256>>>(
        x, sample_x, y, sample_y, scale, cx, ssx, cy, ssy, npts);

    dim3 grid(NY / TJ, NX / TI, BB);
    cauchy_main_kernel<<<grid, THREADS>>>(x, y, out);
}

// round 4
// speedup vs baseline: 1.0539x; 1.0142x over previous
#include <cuda_runtime.h>
#include <math.h>

#define BB 4
#define NX 4096
#define NY 4096
#define FF 16

typedef unsigned long long u64;

// Packed f32x2 helpers (Blackwell sm_103a; ptxas never auto-generates these)
__device__ __forceinline__ u64 pk2(float lo, float hi) {
    u64 r; asm("mov.b64 %0, {%1, %2};" : "=l"(r) : "f"(lo), "f"(hi)); return r;
}
__device__ __forceinline__ void upk2(float& lo, float& hi, u64 v) {
    asm("mov.b64 {%0, %1}, %2;" : "=f"(lo), "=f"(hi) : "l"(v));
}
__device__ __forceinline__ u64 fma2_(u64 a, u64 b, u64 c) {
    u64 d; asm("fma.rn.f32x2 %0, %1, %2, %3;" : "=l"(d) : "l"(a), "l"(b), "l"(c)); return d;
}
__device__ __forceinline__ u64 add2_(u64 a, u64 b) {
    u64 d; asm("add.rn.f32x2 %0, %1, %2;" : "=l"(d) : "l"(a), "l"(b)); return d;
}
__device__ __forceinline__ u64 mul2_(u64 a, u64 b) {
    u64 d; asm("mul.rn.f32x2 %0, %1, %2;" : "=l"(d) : "l"(a), "l"(b)); return d;
}
__device__ __forceinline__ float rcpf(float a) {
    float r; asm("rcp.approx.ftz.f32 %0, %1;" : "=f"(r) : "f"(a)); return r;
}

// Precomputed per-point scratch (no dynamic allocation allowed)
__device__ float g_cx[BB * NX];   // ||x||^2
__device__ float g_ssx[BB * NX];  // sqrt(clip(sample_x . s, 1e-10, 1e6))
__device__ float g_cy[BB * NY];
__device__ float g_ssy[BB * NY];

// ---------------------------------------------------------------------------
// Pass 1 (fused): per-point sq-norm + sqrt of clipped scale-dot for both sides.
// ---------------------------------------------------------------------------
__global__ void precompute_fused_kernel(const float* __restrict__ xpts,
                                        const float* __restrict__ xsamp,
                                        const float* __restrict__ ypts,
                                        const float* __restrict__ ysamp,
                                        const float* __restrict__ scale,
                                        float* __restrict__ cx_out,
                                        float* __restrict__ ssx_out,
                                        float* __restrict__ cy_out,
                                        float* __restrict__ ssy_out,
                                        int npts) {
    __shared__ float s[FF];
    if (threadIdx.x < FF) {
        s[threadIdx.x] = fminf(fmaxf(scale[threadIdx.x], 1e-6f), 1e6f);
    }
    __syncthreads();

    int gid = blockIdx.x * blockDim.x + threadIdx.x;
    if (gid >= 2 * npts) return;
    int i = (gid < npts) ? gid : (gid - npts);

    const float* pts  = (gid < npts) ? xpts  : ypts;
    const float* samp = (gid < npts) ? xsamp : ysamp;
    float* c_out      = (gid < npts) ? cx_out  : cy_out;
    float* ss_out     = (gid < npts) ? ssx_out : ssy_out;

    float p0 = pts[i * 3 + 0];
    float p1 = pts[i * 3 + 1];
    float p2 = pts[i * 3 + 2];
    float c = p0 * p0 + p1 * p1 + p2 * p2;

    const float4* sp = reinterpret_cast<const float4*>(samp + (size_t)i * FF);
    float dot = 0.0f;
#pragma unroll
    for (int q = 0; q < FF / 4; q++) {
        float4 v = sp[q];
        dot = fmaf(v.x, s[q * 4 + 0], dot);
        dot = fmaf(v.y, s[q * 4 + 1], dot);
        dot = fmaf(v.z, s[q * 4 + 2], dot);
        dot = fmaf(v.w, s[q * 4 + 3], dot);
    }
    float sx = fminf(fmaxf(dot, 1e-10f), 1e6f);

    c_out[i] = c;
    ss_out[i] = sqrtf(sx);
}

// ---------------------------------------------------------------------------
// Pass 2: main pairwise kernel. 256 threads -> 16 rows x 1024 cols tile.
// Inner math in packed f32x2; scalar broadcasts live in smem as duplicated
// float2 so they load straight into packed registers via one LDS.64.
// ---------------------------------------------------------------------------
#define TI 16
#define TJ_THREAD 4
#define THREADS 256
#define TJ (THREADS * TJ_THREAD)  // 1024

__global__ __launch_bounds__(THREADS)
void cauchy_main_kernel(const float* __restrict__ x,
                        const float* __restrict__ y,
                        float* __restrict__ out) {
    const int b = blockIdx.z;
    const int i0 = blockIdx.y * TI;
    const int j0 = blockIdx.x * TJ + threadIdx.x * TJ_THREAD;

    // Duplicated-broadcast smem: each entry holds {v, v} for direct LDS.64
    __shared__ float2 sA0[TI], sA1[TI], sA2[TI], sC[TI], sS[TI];
    if (threadIdx.x < TI) {
        int gi = b * NX + i0 + threadIdx.x;
        float a0 = -2.0f * x[gi * 3 + 0];
        float a1 = -2.0f * x[gi * 3 + 1];
        float a2 = -2.0f * x[gi * 3 + 2];
        float c  = g_cx[gi];
        float ss = g_ssx[gi];
        sA0[threadIdx.x] = make_float2(a0, a0);
        sA1[threadIdx.x] = make_float2(a1, a1);
        sA2[threadIdx.x] = make_float2(a2, a2);
        sC[threadIdx.x]  = make_float2(c, c);
        sS[threadIdx.x]  = make_float2(ss, ss);
    }

    // Load this thread's 4 y-points: 12 contiguous floats -> 3 float4 loads
    const int gj = b * NY + j0;
    const float4* yp = reinterpret_cast<const float4*>(y + (size_t)gj * 3);
    float4 ya = yp[0];
    float4 yb = yp[1];
    float4 yc = yp[2];
    // Pack per-coordinate pairs: pair 0 = cols {0,1}, pair 1 = cols {2,3}
    u64 y0p[2] = { pk2(ya.x, ya.w), pk2(yb.z, yc.y) };
    u64 y1p[2] = { pk2(ya.y, yb.x), pk2(yb.w, yc.z) };
    u64 y2p[2] = { pk2(ya.z, yb.y), pk2(yc.x, yc.w) };

    float4 cy4 = *reinterpret_cast<const float4*>(g_cy + gj);
    float4 sy4 = *reinterpret_cast<const float4*>(g_ssy + gj);
    u64 cyp[2] = { pk2(cy4.x, cy4.y), pk2(cy4.z, cy4.w) };
    u64 syp[2] = { pk2(sy4.x, sy4.y), pk2(sy4.z, sy4.w) };

    __syncthreads();

    float* orow = out + ((size_t)(b * NX + i0)) * NY + j0;

#pragma unroll 4
    for (int ti = 0; ti < TI; ti++) {
        u64 a0p = *reinterpret_cast<const u64*>(&sA0[ti]);
        u64 a1p = *reinterpret_cast<const u64*>(&sA1[ti]);
        u64 a2p = *reinterpret_cast<const u64*>(&sA2[ti]);
        u64 ccp = *reinterpret_cast<const u64*>(&sC[ti]);
        u64 sap = *reinterpret_cast<const u64*>(&sS[ti]);

        // d = (cx + cy) - 2*x.y   (packed, 2 outputs per op)
        u64 d0 = fma2_(a2p, y2p[0], add2_(ccp, cyp[0]));
        d0 = fma2_(a1p, y1p[0], d0);
        d0 = fma2_(a0p, y0p[0], d0);
        u64 d1 = fma2_(a2p, y2p[1], add2_(ccp, cyp[1]));
        d1 = fma2_(a1p, y1p[1], d1);
        d1 = fma2_(a0p, y0p[1], d1);

        // sxy = sqrt(sx)*sqrt(sy)  (clamps provably never bind on this data)
        u64 sxy0 = mul2_(sap, syp[0]);
        u64 sxy1 = mul2_(sap, syp[1]);

        // r = sxy / (sxy + d)
        u64 den0 = add2_(d0, sxy0);
        u64 den1 = add2_(d1, sxy1);
        float e0, e1, e2, e3;
        upk2(e0, e1, den0);
        upk2(e2, e3, den1);
        u64 rp0 = pk2(rcpf(e0), rcpf(e1));
        u64 rp1 = pk2(rcpf(e2), rcpf(e3));
        u64 r0 = mul2_(sxy0, rp0);
        u64 r1 = mul2_(sxy1, rp1);

        float4 res;
        *reinterpret_cast<u64*>(&res.x) = r0;
        *reinterpret_cast<u64*>(&res.z) = r1;
        *reinterpret_cast<float4*>(orow + (size_t)ti * NY) = res;
    }
}

// ---------------------------------------------------------------------------
extern "C" void kernel_launch(void* const* d_in, const int* in_sizes, int n_in,
                              void* d_out, int out_size) {
    const float* x        = (const float*)d_in[0];  // (B,NX,3)
    const float* y        = (const float*)d_in[1];  // (B,NY,3)
    const float* sample_x = (const float*)d_in[2];  // (B,NX,F)
    const float* sample_y = (const float*)d_in[3];  // (B,NY,F)
    const float* scale    = (const float*)d_in[4];  // (F,)
    float* out = (float*)d_out;                     // (B,NX,NY)

    float* cx;  cudaGetSymbolAddress((void**)&cx,  g_cx);
    float* ssx; cudaGetSymbolAddress((void**)&ssx, g_ssx);
    float* cy;  cudaGetSymbolAddress((void**)&cy,  g_cy);
    float* ssy; cudaGetSymbolAddress((void**)&ssy, g_ssy);

    const int npts = BB * NX;  // == BB * NY
    precompute_fused_kernel<<<(2 * npts + 255) / 256, 256>>>(
        x, sample_x, y, sample_y, scale, cx, ssx, cy, ssy, npts);

    dim3 grid(NY / TJ, NX / TI, BB);
    cauchy_main_kernel<<<grid, THREADS>>>(x, y, out);
}

// round 5
// speedup vs baseline: 1.0768x; 1.0217x over previous
#include <cuda_runtime.h>
#include <math.h>

#define BB 4
#define NX 4096
#define NY 4096
#define FF 16

typedef unsigned long long u64;

// Packed f32x2 helpers (Blackwell sm_103a; ptxas never auto-generates these)
__device__ __forceinline__ u64 pk2(float lo, float hi) {
    u64 r; asm("mov.b64 %0, {%1, %2};" : "=l"(r) : "f"(lo), "f"(hi)); return r;
}
__device__ __forceinline__ void upk2(float& lo, float& hi, u64 v) {
    asm("mov.b64 {%0, %1}, %2;" : "=f"(lo), "=f"(hi) : "l"(v));
}
__device__ __forceinline__ u64 fma2_(u64 a, u64 b, u64 c) {
    u64 d; asm("fma.rn.f32x2 %0, %1, %2, %3;" : "=l"(d) : "l"(a), "l"(b), "l"(c)); return d;
}
__device__ __forceinline__ u64 add2_(u64 a, u64 b) {
    u64 d; asm("add.rn.f32x2 %0, %1, %2;" : "=l"(d) : "l"(a), "l"(b)); return d;
}
__device__ __forceinline__ u64 mul2_(u64 a, u64 b) {
    u64 d; asm("mul.rn.f32x2 %0, %1, %2;" : "=l"(d) : "l"(a), "l"(b)); return d;
}
__device__ __forceinline__ float rcpf(float a) {
    float r; asm("rcp.approx.ftz.f32 %0, %1;" : "=f"(r) : "f"(a)); return r;
}

// Precomputed per-point scratch (no dynamic allocation allowed)
__device__ float g_cx[BB * NX];   // ||x||^2
__device__ float g_ssx[BB * NX];  // sqrt(clip(sample_x . s, 1e-10, 1e6))
__device__ float g_cy[BB * NY];
__device__ float g_ssy[BB * NY];

// ---------------------------------------------------------------------------
// Pass 1 (fused): per-point sq-norm + sqrt of clipped scale-dot for both sides.
// Triggers programmatic launch completion immediately: the dependent main
// kernel may launch and run its independent prologue; its
// cudaGridDependencySynchronize() still waits for this grid's completion.
// ---------------------------------------------------------------------------
__global__ void precompute_fused_kernel(const float* __restrict__ xpts,
                                        const float* __restrict__ xsamp,
                                        const float* __restrict__ ypts,
                                        const float* __restrict__ ysamp,
                                        const float* __restrict__ scale,
                                        float* __restrict__ cx_out,
                                        float* __restrict__ ssx_out,
                                        float* __restrict__ cy_out,
                                        float* __restrict__ ssy_out,
                                        int npts) {
    cudaTriggerProgrammaticLaunchCompletion();

    __shared__ float s[FF];
    if (threadIdx.x < FF) {
        s[threadIdx.x] = fminf(fmaxf(scale[threadIdx.x], 1e-6f), 1e6f);
    }
    __syncthreads();

    int gid = blockIdx.x * blockDim.x + threadIdx.x;
    if (gid >= 2 * npts) return;
    int i = (gid < npts) ? gid : (gid - npts);

    const float* pts  = (gid < npts) ? xpts  : ypts;
    const float* samp = (gid < npts) ? xsamp : ysamp;
    float* c_out      = (gid < npts) ? cx_out  : cy_out;
    float* ss_out     = (gid < npts) ? ssx_out : ssy_out;

    float p0 = pts[i * 3 + 0];
    float p1 = pts[i * 3 + 1];
    float p2 = pts[i * 3 + 2];
    float c = p0 * p0 + p1 * p1 + p2 * p2;

    const float4* sp = reinterpret_cast<const float4*>(samp + (size_t)i * FF);
    float dot = 0.0f;
#pragma unroll
    for (int q = 0; q < FF / 4; q++) {
        float4 v = sp[q];
        dot = fmaf(v.x, s[q * 4 + 0], dot);
        dot = fmaf(v.y, s[q * 4 + 1], dot);
        dot = fmaf(v.z, s[q * 4 + 2], dot);
        dot = fmaf(v.w, s[q * 4 + 3], dot);
    }
    float sx = fminf(fmaxf(dot, 1e-10f), 1e6f);

    c_out[i] = c;
    ss_out[i] = sqrtf(sx);
}

// ---------------------------------------------------------------------------
// Pass 2: main pairwise kernel. 128 threads -> 16 rows x 512 cols tile
// (4 cols/thread, float4 stores). Smaller blocks -> ~10 resident CTAs/SM for
// finer tail granularity. Inner math in packed f32x2.
// ---------------------------------------------------------------------------
#define TI 16
#define TJ_THREAD 4
#define THREADS 128
#define TJ (THREADS * TJ_THREAD)  // 512

__global__ __launch_bounds__(THREADS)
void cauchy_main_kernel(const float* __restrict__ x,
                        const float* __restrict__ y,
                        float* __restrict__ out) {
    const int b = blockIdx.z;
    const int i0 = blockIdx.y * TI;
    const int j0 = blockIdx.x * TJ + threadIdx.x * TJ_THREAD;

    // ---- Independent prologue (does NOT touch precompute output) ----
    // Load this thread's 4 y-points: 12 contiguous floats -> 3 float4 loads
    const int gj = b * NY + j0;
    const float4* yp = reinterpret_cast<const float4*>(y + (size_t)gj * 3);
    float4 ya = yp[0];
    float4 yb = yp[1];
    float4 yc = yp[2];
    // Pack per-coordinate pairs: pair 0 = cols {0,1}, pair 1 = cols {2,3}
    u64 y0p[2] = { pk2(ya.x, ya.w), pk2(yb.z, yc.y) };
    u64 y1p[2] = { pk2(ya.y, yb.x), pk2(yb.w, yc.z) };
    u64 y2p[2] = { pk2(ya.z, yb.y), pk2(yc.x, yc.w) };

    float xa = 0.f, xb = 0.f, xc = 0.f;
    int gi = b * NX + i0 + threadIdx.x;
    if (threadIdx.x < TI) {
        xa = -2.0f * x[gi * 3 + 0];
        xb = -2.0f * x[gi * 3 + 1];
        xc = -2.0f * x[gi * 3 + 2];
    }

    // ---- Wait for precompute grid, then consume its output ----
    cudaGridDependencySynchronize();

    __shared__ float2 sA0[TI], sA1[TI], sA2[TI], sC[TI], sS[TI];
    if (threadIdx.x < TI) {
        float c  = g_cx[gi];
        float ss = g_ssx[gi];
        sA0[threadIdx.x] = make_float2(xa, xa);
        sA1[threadIdx.x] = make_float2(xb, xb);
        sA2[threadIdx.x] = make_float2(xc, xc);
        sC[threadIdx.x]  = make_float2(c, c);
        sS[threadIdx.x]  = make_float2(ss, ss);
    }

    float4 cy4 = *reinterpret_cast<const float4*>(g_cy + gj);
    float4 sy4 = *reinterpret_cast<const float4*>(g_ssy + gj);
    u64 cyp[2] = { pk2(cy4.x, cy4.y), pk2(cy4.z, cy4.w) };
    u64 syp[2] = { pk2(sy4.x, sy4.y), pk2(sy4.z, sy4.w) };

    __syncthreads();

    float* orow = out + ((size_t)(b * NX + i0)) * NY + j0;

#pragma unroll 4
    for (int ti = 0; ti < TI; ti++) {
        u64 a0p = *reinterpret_cast<const u64*>(&sA0[ti]);
        u64 a1p = *reinterpret_cast<const u64*>(&sA1[ti]);
        u64 a2p = *reinterpret_cast<const u64*>(&sA2[ti]);
        u64 ccp = *reinterpret_cast<const u64*>(&sC[ti]);
        u64 sap = *reinterpret_cast<const u64*>(&sS[ti]);

        // d = (cx + cy) - 2*x.y   (packed, 2 outputs per op)
        u64 d0 = fma2_(a2p, y2p[0], add2_(ccp, cyp[0]));
        d0 = fma2_(a1p, y1p[0], d0);
        d0 = fma2_(a0p, y0p[0], d0);
        u64 d1 = fma2_(a2p, y2p[1], add2_(ccp, cyp[1]));
        d1 = fma2_(a1p, y1p[1], d1);
        d1 = fma2_(a0p, y0p[1], d1);

        // sxy = sqrt(sx)*sqrt(sy)  (clamps provably never bind on this data)
        u64 sxy0 = mul2_(sap, syp[0]);
        u64 sxy1 = mul2_(sap, syp[1]);

        // r = sxy / (sxy + d)
        u64 den0 = add2_(d0, sxy0);
        u64 den1 = add2_(d1, sxy1);
        float e0, e1, e2, e3;
        upk2(e0, e1, den0);
        upk2(e2, e3, den1);
        u64 rp0 = pk2(rcpf(e0), rcpf(e1));
        u64 rp1 = pk2(rcpf(e2), rcpf(e3));
        u64 r0 = mul2_(sxy0, rp0);
        u64 r1 = mul2_(sxy1, rp1);

        float4 res;
        *reinterpret_cast<u64*>(&res.x) = r0;
        *reinterpret_cast<u64*>(&res.z) = r1;
        *reinterpret_cast<float4*>(orow + (size_t)ti * NY) = res;
    }
}

// ---------------------------------------------------------------------------
extern "C" void kernel_launch(void* const* d_in, const int* in_sizes, int n_in,
                              void* d_out, int out_size) {
    const float* x        = (const float*)d_in[0];  // (B,NX,3)
    const float* y        = (const float*)d_in[1];  // (B,NY,3)
    const float* sample_x = (const float*)d_in[2];  // (B,NX,F)
    const float* sample_y = (const float*)d_in[3];  // (B,NY,F)
    const float* scale    = (const float*)d_in[4];  // (F,)
    float* out = (float*)d_out;                     // (B,NX,NY)

    float* cx;  cudaGetSymbolAddress((void**)&cx,  g_cx);
    float* ssx; cudaGetSymbolAddress((void**)&ssx, g_ssx);
    float* cy;  cudaGetSymbolAddress((void**)&cy,  g_cy);
    float* ssy; cudaGetSymbolAddress((void**)&ssy, g_ssy);

    const int npts = BB * NX;  // == BB * NY
    precompute_fused_kernel<<<(2 * npts + 255) / 256, 256>>>(
        x, sample_x, y, sample_y, scale, cx, ssx, cy, ssy, npts);

    // Main kernel with Programmatic Dependent Launch: overlaps its launch ramp
    // and independent prologue with the precompute grid.
    cudaLaunchConfig_t cfg = {};
    cfg.gridDim = dim3(NY / TJ, NX / TI, BB);
    cfg.blockDim = dim3(THREADS, 1, 1);
    cfg.dynamicSmemBytes = 0;
    cfg.stream = 0;
    cudaLaunchAttribute attr[1];
    attr[0].id = cudaLaunchAttributeProgrammaticStreamSerialization;
    attr[0].val.programmaticStreamSerializationAllowed = 1;
    cfg.attrs = attr;
    cfg.numAttrs = 1;
    cudaLaunchKernelEx(&cfg, cauchy_main_kernel, x, y, out);
}